// round 1
// baseline (speedup 1.0000x reference)
#include <cuda_runtime.h>
#include <cuda_bf16.h>

// RNN_72541997629806: 5-layer stacked LSTM, H=4, SEQ=610, BATCH=128,
// + per-t Linear(4->1) + final FC [5,610] -> out [128,5].
//
// Structure: systolic layer pipeline.
//   grid  = 4 blocks  (each block owns 32 batch elements)
//   block = 160 threads = 5 warps, warp w == LSTM layer w, lane == batch elem
//   step s: layer l processes t = s - l; h handed layer->layer through
//   double-buffered SMEM, one __syncthreads per step.
// All weights register-resident (loop-invariant), c/h recurrence in registers.

#define H 4
#define NUM_LAYERS 5
#define SEQ 610
#define BATCH 128

__device__ __forceinline__ float sigf(float x) {
    // 1/(1+e^-x); __expf = MUFU.EX2 path, overflow-safe (e=inf -> 0)
    float e = __expf(-x);
    return __fdividef(1.0f, 1.0f + e);
}

__device__ __forceinline__ float tanhf_fast(float x) {
    // 2*sigmoid(2x) - 1 ; overflow-safe at both ends
    float e = __expf(-2.0f * x);
    return __fdividef(1.0f - e, 1.0f + e) ;
}

__global__ __launch_bounds__(160, 1)
void lstm_pipeline_kernel(const float* __restrict__ x,      // [128,610,2]
                          const float* __restrict__ w_ih0,  // [16,2]
                          const float* __restrict__ w_ih,   // [4,16,4]
                          const float* __restrict__ w_hh,   // [5,16,4]
                          const float* __restrict__ b_ih,   // [5,16]
                          const float* __restrict__ b_hh,   // [5,16]
                          const float* __restrict__ w_lin,  // [1,4]
                          const float* __restrict__ b_lin,  // [1]
                          const float* __restrict__ w_fc,   // [5,610]
                          const float* __restrict__ b_fc,   // [5]
                          float* __restrict__ out)          // [128,5]
{
    const int lane  = threadIdx.x & 31;
    const int layer = threadIdx.x >> 5;       // 0..4
    const int b     = blockIdx.x * 32 + lane; // batch element

    // ---- load this layer's weights into registers (uniform across lanes) ----
    float wi[16][4];   // input weights (layer 0: [16,2] zero-padded to 4)
    float wh[16][4];   // recurrent weights
    float bias[16];    // b_ih + b_hh

    #pragma unroll
    for (int g = 0; g < 16; ++g) {
        #pragma unroll
        for (int d = 0; d < 4; ++d) {
            if (layer == 0)
                wi[g][d] = (d < 2) ? w_ih0[g * 2 + d] : 0.0f;
            else
                wi[g][d] = w_ih[(((layer - 1) * 16) + g) * 4 + d];
            wh[g][d] = w_hh[((layer * 16) + g) * 4 + d];
        }
        bias[g] = b_ih[layer * 16 + g] + b_hh[layer * 16 + g];
    }

    float wl[4], bl = 0.0f, bfc[5];
    if (layer == 4) {
        #pragma unroll
        for (int d = 0; d < 4; ++d) wl[d] = w_lin[d];
        bl = b_lin[0];
        #pragma unroll
        for (int k = 0; k < 5; ++k) bfc[k] = b_fc[k];
    }

    // ---- state ----
    float h[4] = {0.f, 0.f, 0.f, 0.f};
    float c[4] = {0.f, 0.f, 0.f, 0.f};
    float acc5[5] = {0.f, 0.f, 0.f, 0.f, 0.f};

    // double-buffered per-layer h output: [parity][layer][lane]
    __shared__ float4 hbuf[2][NUM_LAYERS][32];

    const float* xb = x + (size_t)b * SEQ * 2;

    for (int s = 0; s < SEQ + NUM_LAYERS - 1; ++s) {
        __syncthreads();
        int t = s - layer;
        if ((unsigned)t < (unsigned)SEQ) {
            // ---- gather input vector ----
            float inp[4];
            if (layer == 0) {
                float2 xv = *reinterpret_cast<const float2*>(xb + t * 2);
                inp[0] = xv.x; inp[1] = xv.y; inp[2] = 0.0f; inp[3] = 0.0f;
            } else {
                float4 hv = hbuf[(s + 1) & 1][layer - 1][lane];
                inp[0] = hv.x; inp[1] = hv.y; inp[2] = hv.z; inp[3] = hv.w;
            }

            // ---- 16 gates ----
            float gates[16];
            #pragma unroll
            for (int g = 0; g < 16; ++g) {
                float a = bias[g];
                #pragma unroll
                for (int d = 0; d < 4; ++d) a = fmaf(inp[d], wi[g][d], a);
                #pragma unroll
                for (int d = 0; d < 4; ++d) a = fmaf(h[d], wh[g][d], a);
                gates[g] = a;
            }

            // ---- elementwise LSTM update (gate order: i, f, g, o) ----
            #pragma unroll
            for (int j = 0; j < 4; ++j) {
                float ig = sigf(gates[j]);
                float fg = sigf(gates[4 + j]);
                float gg = tanhf_fast(gates[8 + j]);
                float og = sigf(gates[12 + j]);
                c[j] = fmaf(fg, c[j], ig * gg);
                h[j] = og * tanhf_fast(c[j]);
            }

            if (layer < 4) {
                hbuf[s & 1][layer][lane] = make_float4(h[0], h[1], h[2], h[3]);
            } else {
                // per-t Linear(4->1), then on-the-fly FC accumulation
                float st = bl;
                #pragma unroll
                for (int d = 0; d < 4; ++d) st = fmaf(h[d], wl[d], st);
                #pragma unroll
                for (int k = 0; k < 5; ++k)
                    acc5[k] = fmaf(__ldg(&w_fc[k * SEQ + t]), st, acc5[k]);
            }
        }
    }

    if (layer == 4) {
        #pragma unroll
        for (int k = 0; k < 5; ++k)
            out[b * 5 + k] = acc5[k] + bfc[k];
    }
}

extern "C" void kernel_launch(void* const* d_in, const int* in_sizes, int n_in,
                              void* d_out, int out_size) {
    const float* x     = (const float*)d_in[0];
    const float* w_ih0 = (const float*)d_in[1];
    const float* w_ih  = (const float*)d_in[2];
    const float* w_hh  = (const float*)d_in[3];
    const float* b_ih  = (const float*)d_in[4];
    const float* b_hh  = (const float*)d_in[5];
    const float* w_lin = (const float*)d_in[6];
    const float* b_lin = (const float*)d_in[7];
    const float* w_fc  = (const float*)d_in[8];
    const float* b_fc  = (const float*)d_in[9];
    float* out = (float*)d_out;

    lstm_pipeline_kernel<<<BATCH / 32, NUM_LAYERS * 32>>>(
        x, w_ih0, w_ih, w_hh, b_ih, b_hh, w_lin, b_lin, w_fc, b_fc, out);
}

// round 2
// speedup vs baseline: 2.0615x; 2.0615x over previous
#include <cuda_runtime.h>
#include <cuda_bf16.h>

// RNN_72541997629806: 5-layer stacked LSTM (H=4), SEQ=610, BATCH=128,
// per-t Linear(4->1) + final FC [5,610] -> out [128,5].
//
// R2: systolic layer pipeline with gate-sliced lanes.
//   grid  = 16 blocks (8 batch elems each)
//   block = 160 threads = 5 warps; warp w = layer w; lane = (elem, j)
//     elem = lane>>2 (batch element within block), j = lane&3 (hidden idx)
//   Each thread computes gates {i,f,g,o}[j] only (32 FFMA/step vs 128).
//   Own-h all-gather via 3x SHFL.BFLY within the quad (weights permuted
//   j-relative at load so indexing stays lane-invariant).
//   Inter-layer h via double-buffered SMEM + one __syncthreads/step.
//   Activations via MUFU tanh.approx.f32.

#define H 4
#define NUM_LAYERS 5
#define SEQ 610
#define BATCH 128
#define NSTEP (SEQ + NUM_LAYERS - 1)

__device__ __forceinline__ float tanh_fast(float x) {
    float y;
    asm("tanh.approx.f32 %0, %1;" : "=f"(y) : "f"(x));
    return y;
}
__device__ __forceinline__ float sig_fast(float x) {
    return fmaf(0.5f, tanh_fast(0.5f * x), 0.5f);
}
__device__ __forceinline__ float dot4(const float* w, float a, float b, float c, float d) {
    return fmaf(w[3], d, fmaf(w[2], c, fmaf(w[1], b, w[0] * a)));
}

__global__ __launch_bounds__(160, 1)
void lstm_pipeline_kernel(const float* __restrict__ x,      // [128,610,2]
                          const float* __restrict__ w_ih0,  // [16,2]
                          const float* __restrict__ w_ih,   // [4,16,4]
                          const float* __restrict__ w_hh,   // [5,16,4]
                          const float* __restrict__ b_ih,   // [5,16]
                          const float* __restrict__ b_hh,   // [5,16]
                          const float* __restrict__ w_lin,  // [1,4]
                          const float* __restrict__ b_lin,  // [1]
                          const float* __restrict__ w_fc,   // [5,610]
                          const float* __restrict__ b_fc,   // [5]
                          float* __restrict__ out)          // [128,5]
{
    const int tid   = threadIdx.x;
    const int lane  = tid & 31;
    const int layer = tid >> 5;        // 0..4
    const int elem  = lane >> 2;       // 0..7
    const int j     = lane & 3;        // hidden index slice
    const int b     = blockIdx.x * 8 + elem;

    // ---- per-thread weights: gate rows {j, 4+j, 8+j, 12+j} ----
    // wi: absolute column order (input vector is absolute).
    // wh: j-relative permuted columns: whrel[q][d] multiplies h[j^d].
    float wi[4][4], wh[4][4], bs[4];
    #pragma unroll
    for (int q = 0; q < 4; ++q) {
        const int r = q * 4 + j;
        #pragma unroll
        for (int d = 0; d < 4; ++d) {
            wi[q][d] = (layer == 0) ? ((d < 2) ? w_ih0[r * 2 + d] : 0.0f)
                                    : w_ih[(((layer - 1) * 16) + r) * 4 + d];
            wh[q][d] = w_hh[((layer * 16) + r) * 4 + (j ^ d)];   // permuted
        }
        bs[q] = b_ih[layer * 16 + r] + b_hh[layer * 16 + r];
    }

    // layer-4 extras (j-relative permuted w_lin)
    float wl[4], accA = 0.0f, accB = 0.0f;
    if (layer == 4) {
        #pragma unroll
        for (int d = 0; d < 4; ++d) wl[d] = w_lin[j ^ d];
        accA = b_fc[j];                 // lane handles k = j
        if (j == 0) accB = b_fc[4];     // lane j==0 also handles k = 4
    }
    const float blin = (layer == 4) ? b_lin[0] : 0.0f;

    // ---- shared memory ----
    __shared__ float4 hbuf[2][NUM_LAYERS][8];   // parity, layer, elem
    __shared__ float  wfc_s[5 * SEQ];
    for (int i = tid; i < 5 * SEQ; i += 160) wfc_s[i] = w_fc[i];

    // ---- state (j-relative): h0=h[j], h1=h[j^1], h2=h[j^2], h3=h[j^3] ----
    float h0 = 0.f, h1 = 0.f, h2 = 0.f, h3 = 0.f;
    float cj = 0.f;

    // x register prefetch, depth 2 (layer 0 only)
    const float* xb = x + (size_t)b * SEQ * 2;
    float2 xpre[2];
    if (layer == 0) {
        xpre[0] = *reinterpret_cast<const float2*>(xb + 0);
        xpre[1] = *reinterpret_cast<const float2*>(xb + 2);
    }

    for (int s = 0; s < NSTEP; ++s) {
        __syncthreads();   // publishes prev layer's parity buffer
        const int t = s - layer;
        if ((unsigned)t < (unsigned)SEQ) {
            // ---- input vector (absolute order) ----
            float i0, i1, i2, i3;
            if (layer == 0) {
                float2 xv = xpre[t & 1];
                i0 = xv.x; i1 = xv.y; i2 = 0.f; i3 = 0.f;
                int tn = t + 2;
                if (tn < SEQ)
                    xpre[t & 1] = *reinterpret_cast<const float2*>(xb + tn * 2);
            } else {
                float4 hv = hbuf[(s + 1) & 1][layer - 1][elem];
                i0 = hv.x; i1 = hv.y; i2 = hv.z; i3 = hv.w;
            }

            // ---- 4 gates for slice j ----
            float gi = bs[0] + dot4(wi[0], i0, i1, i2, i3) + dot4(wh[0], h0, h1, h2, h3);
            float gf = bs[1] + dot4(wi[1], i0, i1, i2, i3) + dot4(wh[1], h0, h1, h2, h3);
            float gg = bs[2] + dot4(wi[2], i0, i1, i2, i3) + dot4(wh[2], h0, h1, h2, h3);
            float go = bs[3] + dot4(wi[3], i0, i1, i2, i3) + dot4(wh[3], h0, h1, h2, h3);

            float ig = sig_fast(gi);
            float fg = sig_fast(gf);
            float gt = tanh_fast(gg);
            float og = sig_fast(go);
            cj = fmaf(fg, cj, ig * gt);
            const float hj = og * tanh_fast(cj);

            if (layer < 4) {
                // publish to next layer (absolute position j)
                reinterpret_cast<float*>(&hbuf[s & 1][layer][elem])[j] = hj;
            }

            // ---- quad all-gather (j-relative): h0=h[j], h1=h[j^1], ... ----
            h0 = hj;
            h1 = __shfl_xor_sync(0xffffffffu, hj, 1);
            h2 = __shfl_xor_sync(0xffffffffu, hj, 2);
            h3 = __shfl_xor_sync(0xffffffffu, h1, 2);

            if (layer == 4) {
                // st = b_lin + dot(h, w_lin)  (j-relative dot)
                float st = fmaf(wl[3], h3, fmaf(wl[2], h2,
                           fmaf(wl[1], h1, fmaf(wl[0], h0, blin))));
                accA = fmaf(wfc_s[j * SEQ + t], st, accA);
                if (j == 0) accB = fmaf(wfc_s[4 * SEQ + t], st, accB);
            }
        }
    }

    if (layer == 4) {
        out[b * 5 + j] = accA;
        if (j == 0) out[b * 5 + 4] = accB;
    }
}

extern "C" void kernel_launch(void* const* d_in, const int* in_sizes, int n_in,
                              void* d_out, int out_size) {
    const float* x     = (const float*)d_in[0];
    const float* w_ih0 = (const float*)d_in[1];
    const float* w_ih  = (const float*)d_in[2];
    const float* w_hh  = (const float*)d_in[3];
    const float* b_ih  = (const float*)d_in[4];
    const float* b_hh  = (const float*)d_in[5];
    const float* w_lin = (const float*)d_in[6];
    const float* b_lin = (const float*)d_in[7];
    const float* w_fc  = (const float*)d_in[8];
    const float* b_fc  = (const float*)d_in[9];
    float* out = (float*)d_out;

    lstm_pipeline_kernel<<<BATCH / 8, NUM_LAYERS * 32>>>(
        x, w_ih0, w_ih, w_hh, b_ih, b_hh, w_lin, b_lin, w_fc, b_fc, out);
}

// round 3
// speedup vs baseline: 2.6082x; 1.2652x over previous
#include <cuda_runtime.h>
#include <cuda_bf16.h>

// RNN_72541997629806: 5-layer stacked LSTM (H=4), SEQ=610, BATCH=128,
// per-t Linear(4->1) + final FC [5,610] -> out [128,5].
//
// R3: whole systolic pipeline inside ONE warp; one batch element per warp.
//   grid = 128 blocks x 32 threads. lane = layer*4 + j (lanes 20-31 idle).
//   Layer handoff + own-h recurrence are parallel register shuffles of a
//   single published register (hpub). No barriers, no shared memory.
//   Sigmoid 0.5-prescale folded into i/f/o weights.

#define H 4
#define NUM_LAYERS 5
#define SEQ 610
#define BATCH 128
#define NSTEP (SEQ + NUM_LAYERS - 1)   // 614 (even)

__device__ __forceinline__ float tanh_fast(float x) {
    float y;
    asm("tanh.approx.f32 %0, %1;" : "=f"(y) : "f"(x));
    return y;
}
__device__ __forceinline__ float dot4(const float* w, float a, float b, float c, float d) {
    return (fmaf(w[0], a, w[1] * b)) + (fmaf(w[2], c, w[3] * d));
}

__global__ __launch_bounds__(32, 1)
void lstm_warp_kernel(const float* __restrict__ x,      // [128,610,2]
                      const float* __restrict__ w_ih0,  // [16,2]
                      const float* __restrict__ w_ih,   // [4,16,4]
                      const float* __restrict__ w_hh,   // [5,16,4]
                      const float* __restrict__ b_ih,   // [5,16]
                      const float* __restrict__ b_hh,   // [5,16]
                      const float* __restrict__ w_lin,  // [1,4]
                      const float* __restrict__ b_lin,  // [1]
                      const float* __restrict__ w_fc,   // [5,610]
                      const float* __restrict__ b_fc,   // [5]
                      float* __restrict__ out)          // [128,5]
{
    const int lane     = threadIdx.x;
    const int layerRaw = lane >> 2;                  // 0..7
    const int layer    = layerRaw > 4 ? 4 : layerRaw;
    const int j        = lane & 3;
    const int b        = blockIdx.x;                 // batch element

    // ---- per-lane weights: gate rows {j, 4+j, 8+j, 12+j} of its layer ----
    // wh columns permuted j-relative: wh[q][d] multiplies h[j^d].
    // i/f/o gates (q = 0,1,3) pre-scaled by 0.5 for sigmoid-via-tanh.
    float wi[4][4], wh[4][4], bs[4];
    #pragma unroll
    for (int q = 0; q < 4; ++q) {
        const int r = q * 4 + j;
        const float sc = (q == 2) ? 1.0f : 0.5f;
        #pragma unroll
        for (int d = 0; d < 4; ++d) {
            float wiv = (layer == 0) ? ((d < 2) ? w_ih0[r * 2 + d] : 0.0f)
                                     : w_ih[(((layer - 1) * 16) + r) * 4 + d];
            wi[q][d] = sc * wiv;
            wh[q][d] = sc * w_hh[((layer * 16) + r) * 4 + (j ^ d)];
        }
        bs[q] = sc * (b_ih[layer * 16 + r] + b_hh[layer * 16 + r]);
    }

    // layer-4 extras (w_lin permuted j-relative)
    float wl[4], blin, accA = 0.0f, accB = 0.0f;
    #pragma unroll
    for (int d = 0; d < 4; ++d) wl[d] = w_lin[j ^ d];
    blin = b_lin[0];
    if (layerRaw == 4) {
        accA = b_fc[j];
        if (j == 0) accB = b_fc[4];
    }

    // ---- state ----
    float hpub = 0.0f;    // published h[j] of this lane's layer (prev step)
    float cj   = 0.0f;

    const float* xb = x + (size_t)b * SEQ * 2;
    float2 xA = *reinterpret_cast<const float2*>(xb + 0);   // x[0]
    float2 xB = *reinterpret_cast<const float2*>(xb + 2);   // x[1]

    const int prevbase = ((lane & ~3) - 4) & 31;

    #pragma unroll 1
    for (int s = 0; s < NSTEP; s += 2) {
        #pragma unroll
        for (int u = 0; u < 2; ++u) {
            const int ss = s + u;
            // ---- parallel shuffles of last step's published h (all lanes) ----
            const float h0 = hpub;
            const float h1 = __shfl_xor_sync(0xffffffffu, hpub, 1);
            const float h2 = __shfl_xor_sync(0xffffffffu, hpub, 2);
            const float h3 = __shfl_xor_sync(0xffffffffu, hpub, 3);
            const float p0 = __shfl_sync(0xffffffffu, hpub, prevbase);
            const float p1 = __shfl_sync(0xffffffffu, hpub, prevbase + 1);
            const float p2 = __shfl_sync(0xffffffffu, hpub, prevbase + 2);
            const float p3 = __shfl_sync(0xffffffffu, hpub, prevbase + 3);

            const int t = ss - layerRaw;
            const bool active = (lane < 20) && ((unsigned)t < (unsigned)SEQ);

            float i0, i1, i2, i3;
            if (layerRaw == 0) {
                const float2 xv = u ? xB : xA;
                i0 = xv.x; i1 = xv.y; i2 = 0.0f; i3 = 0.0f;
            } else {
                i0 = p0; i1 = p1; i2 = p2; i3 = p3;
            }

            // ---- gates (i,f,o pre-scaled by 0.5) ----
            const float gi = bs[0] + dot4(wi[0], i0, i1, i2, i3) + dot4(wh[0], h0, h1, h2, h3);
            const float gf = bs[1] + dot4(wi[1], i0, i1, i2, i3) + dot4(wh[1], h0, h1, h2, h3);
            const float gg = bs[2] + dot4(wi[2], i0, i1, i2, i3) + dot4(wh[2], h0, h1, h2, h3);
            const float go = bs[3] + dot4(wi[3], i0, i1, i2, i3) + dot4(wh[3], h0, h1, h2, h3);

            const float ig = fmaf(0.5f, tanh_fast(gi), 0.5f);
            const float fg = fmaf(0.5f, tanh_fast(gf), 0.5f);
            const float gt = tanh_fast(gg);
            const float og = fmaf(0.5f, tanh_fast(go), 0.5f);

            const float cn = fmaf(fg, cj, ig * gt);
            const float hn = og * tanh_fast(cn);

            cj   = active ? cn : cj;
            hpub = active ? hn : hpub;

            // ---- layer-4 tail: uniform shuffles, predicated accumulate ----
            const float q1 = __shfl_xor_sync(0xffffffffu, hpub, 1);
            const float q2 = __shfl_xor_sync(0xffffffffu, hpub, 2);
            const float q3 = __shfl_xor_sync(0xffffffffu, hpub, 3);
            if (layerRaw == 4 && (unsigned)t < (unsigned)SEQ) {
                const float st = fmaf(wl[3], q3, fmaf(wl[2], q2,
                                 fmaf(wl[1], q1, fmaf(wl[0], hpub, blin))));
                accA = fmaf(__ldg(&w_fc[j * SEQ + t]), st, accA);
                if (j == 0) accB = fmaf(__ldg(&w_fc[4 * SEQ + t]), st, accB);
            }

            // prefetch x two steps ahead into the consumed slot
            {
                const int tn = ss + 2;
                const float2 v = *reinterpret_cast<const float2*>(
                    xb + (tn < SEQ ? tn : SEQ - 1) * 2);
                if (u == 0) xA = v; else xB = v;
            }
        }
    }

    if (layerRaw == 4) {
        out[b * 5 + j] = accA;
        if (j == 0) out[b * 5 + 4] = accB;
    }
}

extern "C" void kernel_launch(void* const* d_in, const int* in_sizes, int n_in,
                              void* d_out, int out_size) {
    const float* x     = (const float*)d_in[0];
    const float* w_ih0 = (const float*)d_in[1];
    const float* w_ih  = (const float*)d_in[2];
    const float* w_hh  = (const float*)d_in[3];
    const float* b_ih  = (const float*)d_in[4];
    const float* b_hh  = (const float*)d_in[5];
    const float* w_lin = (const float*)d_in[6];
    const float* b_lin = (const float*)d_in[7];
    const float* w_fc  = (const float*)d_in[8];
    const float* b_fc  = (const float*)d_in[9];
    float* out = (float*)d_out;

    lstm_warp_kernel<<<BATCH, 32>>>(
        x, w_ih0, w_ih, w_hh, b_ih, b_hh, w_lin, b_lin, w_fc, b_fc, out);
}